// round 1
// baseline (speedup 1.0000x reference)
#include <cuda_runtime.h>
#include <math.h>

#define BB 2
#define NN 4096
#define HH 16
#define DD 64
#define CC 1024
#define BN (BB*NN)            // 8192 tokens
#define TOK 128               // tokens per block in argmax kernel

// Scratch (no cudaMalloc allowed): projected codebook keys/values + histogram.
__device__ __align__(16) float g_k[HH*CC*DD];   // 4 MB
__device__ __align__(16) float g_v[HH*CC*DD];   // 4 MB
__device__ int g_hist[HH*CC];

// ---------------------------------------------------------------------------
// Phase A: k = codebooks @ wk, v = codebooks @ wv   (per head, 1024x64x64)
// grid (H, C/16), block 256. wk/wv head matrices staged in smem.
// ---------------------------------------------------------------------------
__global__ void kv_kernel(const float* __restrict__ cb,
                          const float* __restrict__ wk,
                          const float* __restrict__ wv) {
    int h  = blockIdx.x;
    int c0 = blockIdx.y * 16;
    __shared__ float s_wk[DD*DD];
    __shared__ float s_wv[DD*DD];
    __shared__ float s_cb[16*DD];
    int tid = threadIdx.x;
    for (int i = tid; i < DD*DD; i += 256) {
        s_wk[i] = wk[h*DD*DD + i];
        s_wv[i] = wv[h*DD*DD + i];
    }
    for (int i = tid; i < 16*DD; i += 256) {
        s_cb[i] = cb[(size_t)h*CC*DD + (size_t)c0*DD + i];
    }
    __syncthreads();
    int d  = tid & 63;        // output dim
    int cl = tid >> 6;        // 0..3
    for (int cc = cl; cc < 16; cc += 4) {
        float ak = 0.f, av = 0.f;
        #pragma unroll
        for (int e = 0; e < DD; e++) {
            float cbe = s_cb[cc*DD + e];     // broadcast within warp
            ak = fmaf(cbe, s_wk[e*DD + d], ak);
            av = fmaf(cbe, s_wv[e*DD + d], av);
        }
        size_t off = ((size_t)h*CC + (c0 + cc))*DD + d;
        g_k[off] = ak;
        g_v[off] = av;
    }
}

__global__ void zero_hist_kernel() {
    int i = blockIdx.x * 256 + threadIdx.x;
    if (i < HH*CC) g_hist[i] = 0;
}

// ---------------------------------------------------------------------------
// Phase B: fused logits + argmax + v-gather + index write + histogram.
// grid (BN/TOK, H), block TOK. One thread = one token for head h.
// q (64 floats) lives in registers; K tiles of 128x64 staged in smem.
// All lanes walk (j,d) in lockstep -> LDS.128 broadcast (conflict-free).
// ---------------------------------------------------------------------------
__global__ void __launch_bounds__(TOK)
argmax_kernel(const float* __restrict__ x, float* __restrict__ out_base) {
    int h = blockIdx.y;
    int t = blockIdx.x * TOK + threadIdx.x;      // token id in [0, BN)

    __shared__ float4 s_k[128 * 16];             // 128 codes x 64 dims

    // load q = x[b, i, h*64 + d] * D^-0.5  (t*1024 + h*64 contiguous 256B)
    float4 q[16];
    const float4* xq = (const float4*)(x + (size_t)t * (HH*DD) + h*DD);
    #pragma unroll
    for (int i = 0; i < 16; i++) {
        float4 v = xq[i];
        v.x *= 0.125f; v.y *= 0.125f; v.z *= 0.125f; v.w *= 0.125f;
        q[i] = v;
    }

    float best = -INFINITY;
    int   bi   = 0;

    for (int jt = 0; jt < CC; jt += 128) {
        __syncthreads();
        const float4* ks = (const float4*)(g_k + ((size_t)h*CC + jt)*DD);
        for (int i = threadIdx.x; i < 128*16; i += TOK) s_k[i] = ks[i];
        __syncthreads();

        #pragma unroll 4
        for (int j = 0; j < 128; j++) {
            float a0 = 0.f, a1 = 0.f, a2 = 0.f, a3 = 0.f;
            #pragma unroll
            for (int d4 = 0; d4 < 16; d4 += 4) {
                float4 k0 = s_k[j*16 + d4 + 0];
                float4 k1 = s_k[j*16 + d4 + 1];
                float4 k2 = s_k[j*16 + d4 + 2];
                float4 k3 = s_k[j*16 + d4 + 3];
                a0 = fmaf(q[d4+0].x, k0.x, a0); a0 = fmaf(q[d4+0].y, k0.y, a0);
                a0 = fmaf(q[d4+0].z, k0.z, a0); a0 = fmaf(q[d4+0].w, k0.w, a0);
                a1 = fmaf(q[d4+1].x, k1.x, a1); a1 = fmaf(q[d4+1].y, k1.y, a1);
                a1 = fmaf(q[d4+1].z, k1.z, a1); a1 = fmaf(q[d4+1].w, k1.w, a1);
                a2 = fmaf(q[d4+2].x, k2.x, a2); a2 = fmaf(q[d4+2].y, k2.y, a2);
                a2 = fmaf(q[d4+2].z, k2.z, a2); a2 = fmaf(q[d4+2].w, k2.w, a2);
                a3 = fmaf(q[d4+3].x, k3.x, a3); a3 = fmaf(q[d4+3].y, k3.y, a3);
                a3 = fmaf(q[d4+3].z, k3.z, a3); a3 = fmaf(q[d4+3].w, k3.w, a3);
            }
            float acc = (a0 + a1) + (a2 + a3);
            if (acc > best) { best = acc; bi = jt + j; }  // first-max semantics
        }
    }

    // gather v row -> out[b, i, h*64 + d]
    const float4* vrow = (const float4*)(g_v + ((size_t)h*CC + bi)*DD);
    float4* orow = (float4*)(out_base + (size_t)t * (HH*DD) + h*DD);
    #pragma unroll
    for (int i = 0; i < 16; i++) orow[i] = vrow[i];

    // codebook index: layout (b, h, i) as float
    int b = t / NN, ii = t - b*NN;
    float* idx_out = out_base + (size_t)BB*NN*HH*DD;
    idx_out[((size_t)b*HH + h)*NN + ii] = (float)bi;

    atomicAdd(&g_hist[h*CC + bi], 1);
}

// ---------------------------------------------------------------------------
// Phase C: perplexity per head from histogram. grid H, block 256.
// ---------------------------------------------------------------------------
__global__ void perp_kernel(float* __restrict__ out_base) {
    int h = blockIdx.x;
    __shared__ float red[256];
    float s = 0.f;
    const float inv = 1.0f / (float)BN;
    for (int c = threadIdx.x; c < CC; c += 256) {
        float m = (float)g_hist[h*CC + c] * inv;
        s += m * logf(m + 1e-10f);
    }
    red[threadIdx.x] = s;
    __syncthreads();
    for (int o = 128; o > 0; o >>= 1) {
        if (threadIdx.x < o) red[threadIdx.x] += red[threadIdx.x + o];
        __syncthreads();
    }
    if (threadIdx.x == 0) {
        size_t perp_off = (size_t)BB*NN*HH*DD + (size_t)BB*HH*NN;
        out_base[perp_off + h] = expf(-red[0]);
    }
}

// ---------------------------------------------------------------------------
extern "C" void kernel_launch(void* const* d_in, const int* in_sizes, int n_in,
                              void* d_out, int out_size) {
    const float* x  = (const float*)d_in[0];   // (B, N, H*D)
    const float* cb = (const float*)d_in[1];   // (H, C, D)
    const float* wk = (const float*)d_in[2];   // (H, D, D)
    const float* wv = (const float*)d_in[3];   // (H, D, D)
    float* out = (float*)d_out;

    zero_hist_kernel<<<(HH*CC + 255)/256, 256>>>();

    dim3 gkv(HH, CC/16);
    kv_kernel<<<gkv, 256>>>(cb, wk, wv);

    dim3 gb(BN/TOK, HH);
    argmax_kernel<<<gb, TOK>>>(x, out);

    perp_kernel<<<HH, 256>>>(out);
}